// round 14
// baseline (speedup 1.0000x reference)
#include <cuda_runtime.h>
#include <math.h>

#define Ld 2048
#define Sd 2048
#define NBd 4
#define Ed 512
#define Hd 8
#define Dd 64
#define Md (Ld * NBd)
#define BATCHd (NBd * Hd)

typedef unsigned long long u64;

// Scratch (static device globals — allocation-free per harness rules)
__device__ float g_q[(size_t)BATCHd * Ld * Dd];     // [n][h][l][d], q already +rel_u, *1/8
__device__ float g_k[(size_t)BATCHd * Sd * Dd];
__device__ float g_v[(size_t)BATCHd * Sd * Dd];
__device__ float g_sc[(size_t)BATCHd * Ld * Sd];    // scores/probs, 512 MB
__device__ float g_ao[(size_t)Md * Ed];             // attention output (L,N,E)

// ---- packed dual-fp32 FMA (sm_103a FFMA2; ptxas never auto-emits) -------
__device__ __forceinline__ u64 ffma2(u64 a, u64 b, u64 c) {
    u64 d;
    asm("fma.rn.f32x2 %0, %1, %2, %3;" : "=l"(d) : "l"(a), "l"(b), "l"(c));
    return d;
}
__device__ __forceinline__ float dlo(u64 d) { return __uint_as_float((unsigned)d); }
__device__ __forceinline__ float dhi(u64 d) { return __uint_as_float((unsigned)(d >> 32)); }
__device__ __forceinline__ u64 dup2(float f) {
    u64 d; unsigned b = __float_as_uint(f);
    asm("mov.b64 %0, {%1, %1};" : "=l"(d) : "r"(b));
    return d;
}

// ===========================================================================
// qk: scores[b][l][s] = sum_d q[b][l][d]*k[b][s][d]
// 256 thr: tx = tid&31 over s (tx*4), ty = tid>>5 over 8 l-groups (16 rows).
// Tile 128l x 128s, K=64 resident. Micro 8 l-pairs x 4 s. 2 CTAs/SM -> 16 warps.
// ===========================================================================
#define QK_SA 132
#define QK_SB 132
__global__ void __launch_bounds__(256, 2) qk5_kernel()
{
    extern __shared__ float sm[];
    float* Qs = sm;                 // [64][132]  ([d][l])
    float* Ks = sm + 64 * QK_SA;    // [64][132]  ([d][s], natural)

    int tid = threadIdx.x;
    int s0 = blockIdx.x * 128, l0 = blockIdx.y * 128, b = blockIdx.z;
    const float* Q = g_q + (size_t)b * Ld * Dd;
    const float* K = g_k + (size_t)b * Sd * Dd;

    // load+transpose Q (128x64 -> Qs[d][l]); 512 4x4 blocks, 2/thread
    #pragma unroll
    for (int u = 0; u < 2; u++) {
        int blk = tid + u * 256;
        int d4 = (blk & 15) * 4, l4 = (blk >> 4) * 4;
        float4 r0 = *(const float4*)(Q + (size_t)(l0 + l4 + 0) * Dd + d4);
        float4 r1 = *(const float4*)(Q + (size_t)(l0 + l4 + 1) * Dd + d4);
        float4 r2 = *(const float4*)(Q + (size_t)(l0 + l4 + 2) * Dd + d4);
        float4 r3 = *(const float4*)(Q + (size_t)(l0 + l4 + 3) * Dd + d4);
        *(float4*)(Qs + (d4 + 0) * QK_SA + l4) = make_float4(r0.x, r1.x, r2.x, r3.x);
        *(float4*)(Qs + (d4 + 1) * QK_SA + l4) = make_float4(r0.y, r1.y, r2.y, r3.y);
        *(float4*)(Qs + (d4 + 2) * QK_SA + l4) = make_float4(r0.z, r1.z, r2.z, r3.z);
        *(float4*)(Qs + (d4 + 3) * QK_SA + l4) = make_float4(r0.w, r1.w, r2.w, r3.w);
    }
    // load+transpose K (128x64 -> Ks[d][s], natural)
    #pragma unroll
    for (int u = 0; u < 2; u++) {
        int blk = tid + u * 256;
        int d4 = (blk & 15) * 4, s4 = (blk >> 4) * 4;
        float4 r0 = *(const float4*)(K + (size_t)(s0 + s4 + 0) * Dd + d4);
        float4 r1 = *(const float4*)(K + (size_t)(s0 + s4 + 1) * Dd + d4);
        float4 r2 = *(const float4*)(K + (size_t)(s0 + s4 + 2) * Dd + d4);
        float4 r3 = *(const float4*)(K + (size_t)(s0 + s4 + 3) * Dd + d4);
        *(float4*)(Ks + (d4 + 0) * QK_SB + s4) = make_float4(r0.x, r1.x, r2.x, r3.x);
        *(float4*)(Ks + (d4 + 1) * QK_SB + s4) = make_float4(r0.y, r1.y, r2.y, r3.y);
        *(float4*)(Ks + (d4 + 2) * QK_SB + s4) = make_float4(r0.z, r1.z, r2.z, r3.z);
        *(float4*)(Ks + (d4 + 3) * QK_SB + s4) = make_float4(r0.w, r1.w, r2.w, r3.w);
    }
    __syncthreads();

    int tx = tid & 31, ty = tid >> 5;
    int rb = ty * 16;                // 8 l-pairs = 16 rows
    u64 acc[8][4] = {};

    #pragma unroll 4
    for (int k = 0; k < 64; k++) {
        const ulonglong2* Ad = (const ulonglong2*)(Qs + k * QK_SA + rb);
        u64 a[8], bb[4];
        ulonglong2 t;
        t = Ad[0]; a[0] = t.x; a[1] = t.y;
        t = Ad[1]; a[2] = t.x; a[3] = t.y;
        t = Ad[2]; a[4] = t.x; a[5] = t.y;
        t = Ad[3]; a[6] = t.x; a[7] = t.y;
        float4 b0 = *(const float4*)(Ks + k * QK_SB + tx * 4);
        bb[0] = dup2(b0.x); bb[1] = dup2(b0.y); bb[2] = dup2(b0.z); bb[3] = dup2(b0.w);
        #pragma unroll
        for (int i = 0; i < 8; i++)
            #pragma unroll
            for (int j = 0; j < 4; j++)
                acc[i][j] = ffma2(a[i], bb[j], acc[i][j]);
    }

    float* out = g_sc + (size_t)b * Ld * Sd;
    #pragma unroll
    for (int i = 0; i < 8; i++) {
        int l_lo = l0 + rb + 2 * i;
        float* r0 = out + (size_t)l_lo * Sd + s0 + tx * 4;
        float* r1 = out + (size_t)(l_lo + 1) * Sd + s0 + tx * 4;
        *(float4*)(r0) = make_float4(dlo(acc[i][0]), dlo(acc[i][1]), dlo(acc[i][2]), dlo(acc[i][3]));
        *(float4*)(r1) = make_float4(dhi(acc[i][0]), dhi(acc[i][1]), dhi(acc[i][2]), dhi(acc[i][3]));
    }
}

// ===========================================================================
// pv: out[b][l][d] = sum_s P[b][l][s]*V[b][s][d]  -> g_ao (L,N,E)
// 256 thr: tx = tid&15 over d (tx*4), ty = tid>>4 over 16 l-groups (16 rows).
// Tile 256l x 64d, k-tile 32. 2 CTAs/SM -> 16 warps.
// ===========================================================================
#define PV_SA 260
#define PV_SB 68
__global__ void __launch_bounds__(256, 2) pv5_kernel()
{
    extern __shared__ float sm[];
    float* Ps = sm;                 // [32][260]  ([s'][l])
    float* Vs = sm + 32 * PV_SA;    // [32][68]   ([s'][d], natural)

    int tid = threadIdx.x;
    int l0 = blockIdx.x * 256, b = blockIdx.y;
    int n = b >> 3, h = b & 7;
    const float* P = g_sc + (size_t)b * Ld * Sd;
    const float* V = g_v + (size_t)b * Sd * Dd;

    int tx = tid & 15, ty = tid >> 4;
    int rb = ty * 16;
    u64 acc[8][4] = {};

    for (int st = 0; st < Sd; st += 32) {
        __syncthreads();
        // transpose P (256x32 -> Ps[s'][l]); 512 4x4 blocks, 2/thread
        #pragma unroll
        for (int u = 0; u < 2; u++) {
            int blk = tid + u * 256;
            int s4 = (blk & 7) * 4, m4 = (blk >> 3) * 4;
            float4 r0 = *(const float4*)(P + (size_t)(l0 + m4 + 0) * Sd + st + s4);
            float4 r1 = *(const float4*)(P + (size_t)(l0 + m4 + 1) * Sd + st + s4);
            float4 r2 = *(const float4*)(P + (size_t)(l0 + m4 + 2) * Sd + st + s4);
            float4 r3 = *(const float4*)(P + (size_t)(l0 + m4 + 3) * Sd + st + s4);
            *(float4*)(Ps + (s4 + 0) * PV_SA + m4) = make_float4(r0.x, r1.x, r2.x, r3.x);
            *(float4*)(Ps + (s4 + 1) * PV_SA + m4) = make_float4(r0.y, r1.y, r2.y, r3.y);
            *(float4*)(Ps + (s4 + 2) * PV_SA + m4) = make_float4(r0.z, r1.z, r2.z, r3.z);
            *(float4*)(Ps + (s4 + 3) * PV_SA + m4) = make_float4(r0.w, r1.w, r2.w, r3.w);
        }
        // copy V (32x64 -> Vs natural); 512 float4, 2/thread
        #pragma unroll
        for (int u = 0; u < 2; u++) {
            int idx = tid + u * 256;
            int d4 = (idx & 15) * 4, r = idx >> 4;
            *(float4*)(Vs + r * PV_SB + d4) = *(const float4*)(V + (size_t)(st + r) * Dd + d4);
        }
        __syncthreads();

        #pragma unroll 4
        for (int k = 0; k < 32; k++) {
            const ulonglong2* Ad = (const ulonglong2*)(Ps + k * PV_SA + rb);
            u64 a[8], bb[4];
            ulonglong2 t;
            t = Ad[0]; a[0] = t.x; a[1] = t.y;
            t = Ad[1]; a[2] = t.x; a[3] = t.y;
            t = Ad[2]; a[4] = t.x; a[5] = t.y;
            t = Ad[3]; a[6] = t.x; a[7] = t.y;
            float4 b0 = *(const float4*)(Vs + k * PV_SB + tx * 4);
            bb[0] = dup2(b0.x); bb[1] = dup2(b0.y); bb[2] = dup2(b0.z); bb[3] = dup2(b0.w);
            #pragma unroll
            for (int i = 0; i < 8; i++)
                #pragma unroll
                for (int j = 0; j < 4; j++)
                    acc[i][j] = ffma2(a[i], bb[j], acc[i][j]);
        }
    }

    #pragma unroll
    for (int i = 0; i < 8; i++) {
        int l_lo = l0 + rb + 2 * i;
        float* r0 = g_ao + ((size_t)l_lo * NBd + n) * Ed + h * Dd + tx * 4;
        float* r1 = g_ao + ((size_t)(l_lo + 1) * NBd + n) * Ed + h * Dd + tx * 4;
        *(float4*)(r0) = make_float4(dlo(acc[i][0]), dlo(acc[i][1]), dlo(acc[i][2]), dlo(acc[i][3]));
        *(float4*)(r1) = make_float4(dhi(acc[i][0]), dhi(acc[i][1]), dhi(acc[i][2]), dhi(acc[i][3]));
    }
}

// ===========================================================================
// proj: Y = X @ W^T + bias (optionally +rel, *scale)
// 256 thr, tile 256m x 64e, k-tile 32, K=512. Same micro-kernel as pv.
// mode 0/1/2 -> scatter to g_q/g_k/g_v as [n][h][l][d]; mode 3 -> plain out.
// ===========================================================================
#define PJ_SA 260
#define PJ_SB 68
__global__ void __launch_bounds__(256, 2) proj5_kernel(
    const float* __restrict__ X, const float* __restrict__ W,
    const float* __restrict__ bias, const float* __restrict__ rel,
    float scale, int mode, float* __restrict__ outp)
{
    extern __shared__ float sm[];
    float* Xs = sm;                 // [32][260]
    float* Ws = sm + 32 * PJ_SA;    // [32][68]  (natural)
    const float* Xp = (mode == 3) ? (const float*)g_ao : X;

    int tid = threadIdx.x;
    int e0 = blockIdx.x * 64, m0 = blockIdx.y * 256;
    int tx = tid & 15, ty = tid >> 4;
    int rb = ty * 16;
    u64 acc[8][4] = {};

    for (int kt = 0; kt < Ed; kt += 32) {
        __syncthreads();
        // transpose X (256x32 -> Xs[k'][m]); 2 blocks/thread
        #pragma unroll
        for (int u = 0; u < 2; u++) {
            int blk = tid + u * 256;
            int k4 = (blk & 7) * 4, m4 = (blk >> 3) * 4;
            float4 r0 = *(const float4*)(Xp + (size_t)(m0 + m4 + 0) * Ed + kt + k4);
            float4 r1 = *(const float4*)(Xp + (size_t)(m0 + m4 + 1) * Ed + kt + k4);
            float4 r2 = *(const float4*)(Xp + (size_t)(m0 + m4 + 2) * Ed + kt + k4);
            float4 r3 = *(const float4*)(Xp + (size_t)(m0 + m4 + 3) * Ed + kt + k4);
            *(float4*)(Xs + (k4 + 0) * PJ_SA + m4) = make_float4(r0.x, r1.x, r2.x, r3.x);
            *(float4*)(Xs + (k4 + 1) * PJ_SA + m4) = make_float4(r0.y, r1.y, r2.y, r3.y);
            *(float4*)(Xs + (k4 + 2) * PJ_SA + m4) = make_float4(r0.z, r1.z, r2.z, r3.z);
            *(float4*)(Xs + (k4 + 3) * PJ_SA + m4) = make_float4(r0.w, r1.w, r2.w, r3.w);
        }
        // transpose W (64e x 32k -> Ws[k'][e], natural); 128 blocks, tid<128
        if (tid < 128) {
            int k4 = (tid & 7) * 4, e4 = (tid >> 3) * 4;
            float4 w0 = *(const float4*)(W + (size_t)(e0 + e4 + 0) * Ed + kt + k4);
            float4 w1 = *(const float4*)(W + (size_t)(e0 + e4 + 1) * Ed + kt + k4);
            float4 w2 = *(const float4*)(W + (size_t)(e0 + e4 + 2) * Ed + kt + k4);
            float4 w3 = *(const float4*)(W + (size_t)(e0 + e4 + 3) * Ed + kt + k4);
            *(float4*)(Ws + (k4 + 0) * PJ_SB + e4) = make_float4(w0.x, w1.x, w2.x, w3.x);
            *(float4*)(Ws + (k4 + 1) * PJ_SB + e4) = make_float4(w0.y, w1.y, w2.y, w3.y);
            *(float4*)(Ws + (k4 + 2) * PJ_SB + e4) = make_float4(w0.z, w1.z, w2.z, w3.z);
            *(float4*)(Ws + (k4 + 3) * PJ_SB + e4) = make_float4(w0.w, w1.w, w2.w, w3.w);
        }
        __syncthreads();

        #pragma unroll 4
        for (int k = 0; k < 32; k++) {
            const ulonglong2* Ad = (const ulonglong2*)(Xs + k * PJ_SA + rb);
            u64 a[8], bb[4];
            ulonglong2 t;
            t = Ad[0]; a[0] = t.x; a[1] = t.y;
            t = Ad[1]; a[2] = t.x; a[3] = t.y;
            t = Ad[2]; a[4] = t.x; a[5] = t.y;
            t = Ad[3]; a[6] = t.x; a[7] = t.y;
            float4 b0 = *(const float4*)(Ws + k * PJ_SB + tx * 4);
            bb[0] = dup2(b0.x); bb[1] = dup2(b0.y); bb[2] = dup2(b0.z); bb[3] = dup2(b0.w);
            #pragma unroll
            for (int i = 0; i < 8; i++)
                #pragma unroll
                for (int j = 0; j < 4; j++)
                    acc[i][j] = ffma2(a[i], bb[j], acc[i][j]);
        }
    }

    // epilogue: e index = e0 + tx*4 + j
    float bs[4], rl[4];
    #pragma unroll
    for (int j = 0; j < 4; j++) {
        int e = e0 + tx * 4 + j;
        bs[j] = bias[e];
        rl[j] = rel ? rel[e] : 0.f;
    }
    int hh = e0 >> 6;
    float* dst012 = (mode == 0) ? g_q : (mode == 1) ? g_k : g_v;

    #pragma unroll
    for (int i = 0; i < 8; i++) {
        #pragma unroll
        for (int hp = 0; hp < 2; hp++) {
            int m = m0 + rb + 2 * i + hp;
            float v[4];
            #pragma unroll
            for (int j = 0; j < 4; j++) {
                float x = hp ? dhi(acc[i][j]) : dlo(acc[i][j]);
                v[j] = (x + bs[j] + rl[j]) * scale;
            }
            if (mode < 3) {
                int l = m >> 2, nn = m & 3;
                float* base = dst012 + ((size_t)(nn * Hd + hh) * Ld + l) * Dd + tx * 4;
                *(float4*)(base) = make_float4(v[0], v[1], v[2], v[3]);
            } else {
                float* base = outp + (size_t)m * Ed + e0 + tx * 4;
                *(float4*)(base) = make_float4(v[0], v[1], v[2], v[3]);
            }
        }
    }
}

// ===========================================================================
// Softmax in place over s (per l,n,h) + head-mean -> att_weights
// ===========================================================================
__global__ void __launch_bounds__(256) softmax_kernel(float* __restrict__ attw)
{
    int l = blockIdx.x, n = blockIdx.y;
    int tid = threadIdx.x;
    __shared__ float red[8];
    float mean[8] = {0, 0, 0, 0, 0, 0, 0, 0};

    for (int h = 0; h < Hd; h++) {
        float* row = g_sc + ((size_t)(n * Hd + h) * Ld + l) * Sd;
        float x[8];
        float mx = -1e30f;
        #pragma unroll
        for (int i = 0; i < 8; i++) {
            x[i] = row[tid + (i << 8)];
            mx = fmaxf(mx, x[i]);
        }
        #pragma unroll
        for (int o = 16; o; o >>= 1) mx = fmaxf(mx, __shfl_xor_sync(0xffffffffu, mx, o));
        if ((tid & 31) == 0) red[tid >> 5] = mx;
        __syncthreads();
        if (tid < 32) {
            float w = (tid < 8) ? red[tid] : -1e30f;
            #pragma unroll
            for (int o = 4; o; o >>= 1) w = fmaxf(w, __shfl_xor_sync(0xffffffffu, w, o));
            if (tid == 0) red[0] = w;
        }
        __syncthreads();
        mx = red[0];
        __syncthreads();

        float sum = 0.f;
        #pragma unroll
        for (int i = 0; i < 8; i++) {
            x[i] = __expf(x[i] - mx);
            sum += x[i];
        }
        #pragma unroll
        for (int o = 16; o; o >>= 1) sum += __shfl_xor_sync(0xffffffffu, sum, o);
        if ((tid & 31) == 0) red[tid >> 5] = sum;
        __syncthreads();
        if (tid < 32) {
            float w = (tid < 8) ? red[tid] : 0.f;
            #pragma unroll
            for (int o = 4; o; o >>= 1) w += __shfl_xor_sync(0xffffffffu, w, o);
            if (tid == 0) red[0] = w;
        }
        __syncthreads();
        float inv = 1.0f / red[0];
        __syncthreads();

        #pragma unroll
        for (int i = 0; i < 8; i++) {
            float p = x[i] * inv;
            row[tid + (i << 8)] = p;
            mean[i] += p;
        }
    }

    float* aw = attw + ((size_t)n * Ld + l) * Sd;
    #pragma unroll
    for (int i = 0; i < 8; i++)
        aw[tid + (i << 8)] = mean[i] * 0.125f;
}

// ---------------------------------------------------------------------------
extern "C" void kernel_launch(void* const* d_in, const int* in_sizes, int n_in,
                              void* d_out, int out_size)
{
    const float* query = (const float*)d_in[0];
    const float* key   = (const float*)d_in[1];
    const float* value = (const float*)d_in[2];
    // d_in[3] sin_pos_enc: unused — rel_shift term is constant over the
    // softmax axis in the reference and cancels exactly.
    const float* W     = (const float*)d_in[4];   // (3E, E)
    const float* bias  = (const float*)d_in[5];   // (3E,)
    const float* out_w = (const float*)d_in[6];
    const float* out_b = (const float*)d_in[7];
    // d_in[8] rel_proj_w: unused (cancels)
    const float* rel_u = (const float*)d_in[9];   // (H,D) == E contiguous floats
    // d_in[10] rel_v: unused (cancels)

    float* out  = (float*)d_out;                      // (L, N, E)
    float* attw = out + (size_t)Ld * NBd * Ed;        // (N, L, S)

    const int QK_SMEM = (64 * QK_SA + 64 * QK_SB) * 4;   // 67584 B
    const int PV_SMEM = (32 * PV_SA + 32 * PV_SB) * 4;   // 41984 B
    const int PJ_SMEM = (32 * PJ_SA + 32 * PJ_SB) * 4;   // 41984 B
    cudaFuncSetAttribute(qk5_kernel,   cudaFuncAttributeMaxDynamicSharedMemorySize, QK_SMEM);
    cudaFuncSetAttribute(pv5_kernel,   cudaFuncAttributeMaxDynamicSharedMemorySize, PV_SMEM);
    cudaFuncSetAttribute(proj5_kernel, cudaFuncAttributeMaxDynamicSharedMemorySize, PJ_SMEM);

    dim3 gp(Ed / 64, Md / 256);
    // q_eff = (q + rel_u) / sqrt(D)
    proj5_kernel<<<gp, 256, PJ_SMEM>>>(query, W,               bias,          rel_u,   0.125f, 0, nullptr);
    proj5_kernel<<<gp, 256, PJ_SMEM>>>(key,   W + Ed * Ed,     bias + Ed,     nullptr, 1.0f,   1, nullptr);
    proj5_kernel<<<gp, 256, PJ_SMEM>>>(value, W + 2 * Ed * Ed, bias + 2 * Ed, nullptr, 1.0f,   2, nullptr);

    qk5_kernel<<<dim3(Sd / 128, Ld / 128, BATCHd), 256, QK_SMEM>>>();
    softmax_kernel<<<dim3(Ld, NBd), 256>>>(attw);
    pv5_kernel<<<dim3(Ld / 256, BATCHd), 256, PV_SMEM>>>();

    proj5_kernel<<<gp, 256, PJ_SMEM>>>(nullptr, out_w, out_b, nullptr, 1.0f, 3, out);
}

// round 15
// speedup vs baseline: 1.0024x; 1.0024x over previous
#include <cuda_runtime.h>
#include <math.h>

#define Ld 2048
#define Sd 2048
#define NBd 4
#define Ed 512
#define Hd 8
#define Dd 64
#define Md (Ld * NBd)
#define BATCHd (NBd * Hd)

typedef unsigned long long u64;

// Scratch (static device globals — allocation-free per harness rules)
__device__ float g_q[(size_t)BATCHd * Ld * Dd];     // [n][h][l][d], q already +rel_u, *1/8
__device__ float g_k[(size_t)BATCHd * Sd * Dd];
__device__ float g_v[(size_t)BATCHd * Sd * Dd];
__device__ float g_sc[(size_t)BATCHd * Ld * Sd];    // scores/probs, 512 MB
__device__ float g_ao[(size_t)Md * Ed];             // attention output (L,N,E)

// ---- packed dual-fp32 FMA (sm_103a FFMA2; ptxas never auto-emits) -------
__device__ __forceinline__ u64 ffma2(u64 a, u64 b, u64 c) {
    u64 d;
    asm("fma.rn.f32x2 %0, %1, %2, %3;" : "=l"(d) : "l"(a), "l"(b), "l"(c));
    return d;
}
__device__ __forceinline__ float dlo(u64 d) { return __uint_as_float((unsigned)d); }
__device__ __forceinline__ float dhi(u64 d) { return __uint_as_float((unsigned)(d >> 32)); }
__device__ __forceinline__ u64 dup2(float f) {
    u64 d; unsigned b = __float_as_uint(f);
    asm("mov.b64 %0, {%1, %1};" : "=l"(d) : "r"(b));
    return d;
}

// ===========================================================================
// qk: scores[b][l][s] = sum_d q[b][l][d]*k[b][s][d]
// 256 thr: tx = tid&31 over s (tx*4), ty = tid>>5 over 8 l-groups (16 rows).
// Tile 128l x 128s, K=64 resident. Micro 8 l-pairs x 4 s. 2 CTAs/SM -> 16 warps.
// ===========================================================================
#define QK_SA 132
#define QK_SB 132
__global__ void __launch_bounds__(256, 2) qk5_kernel()
{
    extern __shared__ float sm[];
    float* Qs = sm;                 // [64][132]  ([d][l])
    float* Ks = sm + 64 * QK_SA;    // [64][132]  ([d][s], natural)

    int tid = threadIdx.x;
    int s0 = blockIdx.x * 128, l0 = blockIdx.y * 128, b = blockIdx.z;
    const float* Q = g_q + (size_t)b * Ld * Dd;
    const float* K = g_k + (size_t)b * Sd * Dd;

    // load+transpose Q (128x64 -> Qs[d][l]); 512 4x4 blocks, 2/thread
    #pragma unroll
    for (int u = 0; u < 2; u++) {
        int blk = tid + u * 256;
        int d4 = (blk & 15) * 4, l4 = (blk >> 4) * 4;
        float4 r0 = *(const float4*)(Q + (size_t)(l0 + l4 + 0) * Dd + d4);
        float4 r1 = *(const float4*)(Q + (size_t)(l0 + l4 + 1) * Dd + d4);
        float4 r2 = *(const float4*)(Q + (size_t)(l0 + l4 + 2) * Dd + d4);
        float4 r3 = *(const float4*)(Q + (size_t)(l0 + l4 + 3) * Dd + d4);
        *(float4*)(Qs + (d4 + 0) * QK_SA + l4) = make_float4(r0.x, r1.x, r2.x, r3.x);
        *(float4*)(Qs + (d4 + 1) * QK_SA + l4) = make_float4(r0.y, r1.y, r2.y, r3.y);
        *(float4*)(Qs + (d4 + 2) * QK_SA + l4) = make_float4(r0.z, r1.z, r2.z, r3.z);
        *(float4*)(Qs + (d4 + 3) * QK_SA + l4) = make_float4(r0.w, r1.w, r2.w, r3.w);
    }
    // load+transpose K (128x64 -> Ks[d][s], natural)
    #pragma unroll
    for (int u = 0; u < 2; u++) {
        int blk = tid + u * 256;
        int d4 = (blk & 15) * 4, s4 = (blk >> 4) * 4;
        float4 r0 = *(const float4*)(K + (size_t)(s0 + s4 + 0) * Dd + d4);
        float4 r1 = *(const float4*)(K + (size_t)(s0 + s4 + 1) * Dd + d4);
        float4 r2 = *(const float4*)(K + (size_t)(s0 + s4 + 2) * Dd + d4);
        float4 r3 = *(const float4*)(K + (size_t)(s0 + s4 + 3) * Dd + d4);
        *(float4*)(Ks + (d4 + 0) * QK_SB + s4) = make_float4(r0.x, r1.x, r2.x, r3.x);
        *(float4*)(Ks + (d4 + 1) * QK_SB + s4) = make_float4(r0.y, r1.y, r2.y, r3.y);
        *(float4*)(Ks + (d4 + 2) * QK_SB + s4) = make_float4(r0.z, r1.z, r2.z, r3.z);
        *(float4*)(Ks + (d4 + 3) * QK_SB + s4) = make_float4(r0.w, r1.w, r2.w, r3.w);
    }
    __syncthreads();

    int tx = tid & 31, ty = tid >> 5;
    int rb = ty * 16;                // 8 l-pairs = 16 rows
    u64 acc[8][4] = {};

    #pragma unroll 4
    for (int k = 0; k < 64; k++) {
        const ulonglong2* Ad = (const ulonglong2*)(Qs + k * QK_SA + rb);
        u64 a[8], bb[4];
        ulonglong2 t;
        t = Ad[0]; a[0] = t.x; a[1] = t.y;
        t = Ad[1]; a[2] = t.x; a[3] = t.y;
        t = Ad[2]; a[4] = t.x; a[5] = t.y;
        t = Ad[3]; a[6] = t.x; a[7] = t.y;
        float4 b0 = *(const float4*)(Ks + k * QK_SB + tx * 4);
        bb[0] = dup2(b0.x); bb[1] = dup2(b0.y); bb[2] = dup2(b0.z); bb[3] = dup2(b0.w);
        #pragma unroll
        for (int i = 0; i < 8; i++)
            #pragma unroll
            for (int j = 0; j < 4; j++)
                acc[i][j] = ffma2(a[i], bb[j], acc[i][j]);
    }

    float* out = g_sc + (size_t)b * Ld * Sd;
    #pragma unroll
    for (int i = 0; i < 8; i++) {
        int l_lo = l0 + rb + 2 * i;
        float* r0 = out + (size_t)l_lo * Sd + s0 + tx * 4;
        float* r1 = out + (size_t)(l_lo + 1) * Sd + s0 + tx * 4;
        *(float4*)(r0) = make_float4(dlo(acc[i][0]), dlo(acc[i][1]), dlo(acc[i][2]), dlo(acc[i][3]));
        *(float4*)(r1) = make_float4(dhi(acc[i][0]), dhi(acc[i][1]), dhi(acc[i][2]), dhi(acc[i][3]));
    }
}

// ===========================================================================
// pv: out[b][l][d] = sum_s P[b][l][s]*V[b][s][d]  -> g_ao (L,N,E)
// 256 thr: tx = tid&15 over d (tx*4), ty = tid>>4 over 16 l-groups (16 rows).
// Tile 256l x 64d, k-tile 32. 2 CTAs/SM -> 16 warps.
// ===========================================================================
#define PV_SA 260
#define PV_SB 68
__global__ void __launch_bounds__(256, 2) pv5_kernel()
{
    extern __shared__ float sm[];
    float* Ps = sm;                 // [32][260]  ([s'][l])
    float* Vs = sm + 32 * PV_SA;    // [32][68]   ([s'][d], natural)

    int tid = threadIdx.x;
    int l0 = blockIdx.x * 256, b = blockIdx.y;
    int n = b >> 3, h = b & 7;
    const float* P = g_sc + (size_t)b * Ld * Sd;
    const float* V = g_v + (size_t)b * Sd * Dd;

    int tx = tid & 15, ty = tid >> 4;
    int rb = ty * 16;
    u64 acc[8][4] = {};

    for (int st = 0; st < Sd; st += 32) {
        __syncthreads();
        // transpose P (256x32 -> Ps[s'][l]); 512 4x4 blocks, 2/thread
        #pragma unroll
        for (int u = 0; u < 2; u++) {
            int blk = tid + u * 256;
            int s4 = (blk & 7) * 4, m4 = (blk >> 3) * 4;
            float4 r0 = *(const float4*)(P + (size_t)(l0 + m4 + 0) * Sd + st + s4);
            float4 r1 = *(const float4*)(P + (size_t)(l0 + m4 + 1) * Sd + st + s4);
            float4 r2 = *(const float4*)(P + (size_t)(l0 + m4 + 2) * Sd + st + s4);
            float4 r3 = *(const float4*)(P + (size_t)(l0 + m4 + 3) * Sd + st + s4);
            *(float4*)(Ps + (s4 + 0) * PV_SA + m4) = make_float4(r0.x, r1.x, r2.x, r3.x);
            *(float4*)(Ps + (s4 + 1) * PV_SA + m4) = make_float4(r0.y, r1.y, r2.y, r3.y);
            *(float4*)(Ps + (s4 + 2) * PV_SA + m4) = make_float4(r0.z, r1.z, r2.z, r3.z);
            *(float4*)(Ps + (s4 + 3) * PV_SA + m4) = make_float4(r0.w, r1.w, r2.w, r3.w);
        }
        // copy V (32x64 -> Vs natural); 512 float4, 2/thread
        #pragma unroll
        for (int u = 0; u < 2; u++) {
            int idx = tid + u * 256;
            int d4 = (idx & 15) * 4, r = idx >> 4;
            *(float4*)(Vs + r * PV_SB + d4) = *(const float4*)(V + (size_t)(st + r) * Dd + d4);
        }
        __syncthreads();

        #pragma unroll 4
        for (int k = 0; k < 32; k++) {
            const ulonglong2* Ad = (const ulonglong2*)(Ps + k * PV_SA + rb);
            u64 a[8], bb[4];
            ulonglong2 t;
            t = Ad[0]; a[0] = t.x; a[1] = t.y;
            t = Ad[1]; a[2] = t.x; a[3] = t.y;
            t = Ad[2]; a[4] = t.x; a[5] = t.y;
            t = Ad[3]; a[6] = t.x; a[7] = t.y;
            float4 b0 = *(const float4*)(Vs + k * PV_SB + tx * 4);
            bb[0] = dup2(b0.x); bb[1] = dup2(b0.y); bb[2] = dup2(b0.z); bb[3] = dup2(b0.w);
            #pragma unroll
            for (int i = 0; i < 8; i++)
                #pragma unroll
                for (int j = 0; j < 4; j++)
                    acc[i][j] = ffma2(a[i], bb[j], acc[i][j]);
        }
    }

    #pragma unroll
    for (int i = 0; i < 8; i++) {
        int l_lo = l0 + rb + 2 * i;
        float* r0 = g_ao + ((size_t)l_lo * NBd + n) * Ed + h * Dd + tx * 4;
        float* r1 = g_ao + ((size_t)(l_lo + 1) * NBd + n) * Ed + h * Dd + tx * 4;
        *(float4*)(r0) = make_float4(dlo(acc[i][0]), dlo(acc[i][1]), dlo(acc[i][2]), dlo(acc[i][3]));
        *(float4*)(r1) = make_float4(dhi(acc[i][0]), dhi(acc[i][1]), dhi(acc[i][2]), dhi(acc[i][3]));
    }
}

// ===========================================================================
// proj: Y = X @ W^T + bias (optionally +rel, *scale)
// 256 thr, tile 256m x 64e, k-tile 32, K=512. Same micro-kernel as pv.
// mode 0/1/2 -> scatter to g_q/g_k/g_v as [n][h][l][d]; mode 3 -> plain out.
// ===========================================================================
#define PJ_SA 260
#define PJ_SB 68
__global__ void __launch_bounds__(256, 2) proj5_kernel(
    const float* __restrict__ X, const float* __restrict__ W,
    const float* __restrict__ bias, const float* __restrict__ rel,
    float scale, int mode, float* __restrict__ outp)
{
    extern __shared__ float sm[];
    float* Xs = sm;                 // [32][260]
    float* Ws = sm + 32 * PJ_SA;    // [32][68]  (natural)
    const float* Xp = (mode == 3) ? (const float*)g_ao : X;

    int tid = threadIdx.x;
    int e0 = blockIdx.x * 64, m0 = blockIdx.y * 256;
    int tx = tid & 15, ty = tid >> 4;
    int rb = ty * 16;
    u64 acc[8][4] = {};

    for (int kt = 0; kt < Ed; kt += 32) {
        __syncthreads();
        // transpose X (256x32 -> Xs[k'][m]); 2 blocks/thread
        #pragma unroll
        for (int u = 0; u < 2; u++) {
            int blk = tid + u * 256;
            int k4 = (blk & 7) * 4, m4 = (blk >> 3) * 4;
            float4 r0 = *(const float4*)(Xp + (size_t)(m0 + m4 + 0) * Ed + kt + k4);
            float4 r1 = *(const float4*)(Xp + (size_t)(m0 + m4 + 1) * Ed + kt + k4);
            float4 r2 = *(const float4*)(Xp + (size_t)(m0 + m4 + 2) * Ed + kt + k4);
            float4 r3 = *(const float4*)(Xp + (size_t)(m0 + m4 + 3) * Ed + kt + k4);
            *(float4*)(Xs + (k4 + 0) * PJ_SA + m4) = make_float4(r0.x, r1.x, r2.x, r3.x);
            *(float4*)(Xs + (k4 + 1) * PJ_SA + m4) = make_float4(r0.y, r1.y, r2.y, r3.y);
            *(float4*)(Xs + (k4 + 2) * PJ_SA + m4) = make_float4(r0.z, r1.z, r2.z, r3.z);
            *(float4*)(Xs + (k4 + 3) * PJ_SA + m4) = make_float4(r0.w, r1.w, r2.w, r3.w);
        }
        // transpose W (64e x 32k -> Ws[k'][e], natural); 128 blocks, tid<128
        if (tid < 128) {
            int k4 = (tid & 7) * 4, e4 = (tid >> 3) * 4;
            float4 w0 = *(const float4*)(W + (size_t)(e0 + e4 + 0) * Ed + kt + k4);
            float4 w1 = *(const float4*)(W + (size_t)(e0 + e4 + 1) * Ed + kt + k4);
            float4 w2 = *(const float4*)(W + (size_t)(e0 + e4 + 2) * Ed + kt + k4);
            float4 w3 = *(const float4*)(W + (size_t)(e0 + e4 + 3) * Ed + kt + k4);
            *(float4*)(Ws + (k4 + 0) * PJ_SB + e4) = make_float4(w0.x, w1.x, w2.x, w3.x);
            *(float4*)(Ws + (k4 + 1) * PJ_SB + e4) = make_float4(w0.y, w1.y, w2.y, w3.y);
            *(float4*)(Ws + (k4 + 2) * PJ_SB + e4) = make_float4(w0.z, w1.z, w2.z, w3.z);
            *(float4*)(Ws + (k4 + 3) * PJ_SB + e4) = make_float4(w0.w, w1.w, w2.w, w3.w);
        }
        __syncthreads();

        #pragma unroll 4
        for (int k = 0; k < 32; k++) {
            const ulonglong2* Ad = (const ulonglong2*)(Xs + k * PJ_SA + rb);
            u64 a[8], bb[4];
            ulonglong2 t;
            t = Ad[0]; a[0] = t.x; a[1] = t.y;
            t = Ad[1]; a[2] = t.x; a[3] = t.y;
            t = Ad[2]; a[4] = t.x; a[5] = t.y;
            t = Ad[3]; a[6] = t.x; a[7] = t.y;
            float4 b0 = *(const float4*)(Ws + k * PJ_SB + tx * 4);
            bb[0] = dup2(b0.x); bb[1] = dup2(b0.y); bb[2] = dup2(b0.z); bb[3] = dup2(b0.w);
            #pragma unroll
            for (int i = 0; i < 8; i++)
                #pragma unroll
                for (int j = 0; j < 4; j++)
                    acc[i][j] = ffma2(a[i], bb[j], acc[i][j]);
        }
    }

    // epilogue: e index = e0 + tx*4 + j
    float bs[4], rl[4];
    #pragma unroll
    for (int j = 0; j < 4; j++) {
        int e = e0 + tx * 4 + j;
        bs[j] = bias[e];
        rl[j] = rel ? rel[e] : 0.f;
    }
    int hh = e0 >> 6;
    float* dst012 = (mode == 0) ? g_q : (mode == 1) ? g_k : g_v;

    #pragma unroll
    for (int i = 0; i < 8; i++) {
        #pragma unroll
        for (int hp = 0; hp < 2; hp++) {
            int m = m0 + rb + 2 * i + hp;
            float v[4];
            #pragma unroll
            for (int j = 0; j < 4; j++) {
                float x = hp ? dhi(acc[i][j]) : dlo(acc[i][j]);
                v[j] = (x + bs[j] + rl[j]) * scale;
            }
            if (mode < 3) {
                int l = m >> 2, nn = m & 3;
                float* base = dst012 + ((size_t)(nn * Hd + hh) * Ld + l) * Dd + tx * 4;
                *(float4*)(base) = make_float4(v[0], v[1], v[2], v[3]);
            } else {
                float* base = outp + (size_t)m * Ed + e0 + tx * 4;
                *(float4*)(base) = make_float4(v[0], v[1], v[2], v[3]);
            }
        }
    }
}

// ===========================================================================
// Softmax in place over s (per l,n,h) + head-mean -> att_weights
// ===========================================================================
__global__ void __launch_bounds__(256) softmax_kernel(float* __restrict__ attw)
{
    int l = blockIdx.x, n = blockIdx.y;
    int tid = threadIdx.x;
    __shared__ float red[8];
    float mean[8] = {0, 0, 0, 0, 0, 0, 0, 0};

    for (int h = 0; h < Hd; h++) {
        float* row = g_sc + ((size_t)(n * Hd + h) * Ld + l) * Sd;
        float x[8];
        float mx = -1e30f;
        #pragma unroll
        for (int i = 0; i < 8; i++) {
            x[i] = row[tid + (i << 8)];
            mx = fmaxf(mx, x[i]);
        }
        #pragma unroll
        for (int o = 16; o; o >>= 1) mx = fmaxf(mx, __shfl_xor_sync(0xffffffffu, mx, o));
        if ((tid & 31) == 0) red[tid >> 5] = mx;
        __syncthreads();
        if (tid < 32) {
            float w = (tid < 8) ? red[tid] : -1e30f;
            #pragma unroll
            for (int o = 4; o; o >>= 1) w = fmaxf(w, __shfl_xor_sync(0xffffffffu, w, o));
            if (tid == 0) red[0] = w;
        }
        __syncthreads();
        mx = red[0];
        __syncthreads();

        float sum = 0.f;
        #pragma unroll
        for (int i = 0; i < 8; i++) {
            x[i] = __expf(x[i] - mx);
            sum += x[i];
        }
        #pragma unroll
        for (int o = 16; o; o >>= 1) sum += __shfl_xor_sync(0xffffffffu, sum, o);
        if ((tid & 31) == 0) red[tid >> 5] = sum;
        __syncthreads();
        if (tid < 32) {
            float w = (tid < 8) ? red[tid] : 0.f;
            #pragma unroll
            for (int o = 4; o; o >>= 1) w += __shfl_xor_sync(0xffffffffu, w, o);
            if (tid == 0) red[0] = w;
        }
        __syncthreads();
        float inv = 1.0f / red[0];
        __syncthreads();

        #pragma unroll
        for (int i = 0; i < 8; i++) {
            float p = x[i] * inv;
            row[tid + (i << 8)] = p;
            mean[i] += p;
        }
    }

    float* aw = attw + ((size_t)n * Ld + l) * Sd;
    #pragma unroll
    for (int i = 0; i < 8; i++)
        aw[tid + (i << 8)] = mean[i] * 0.125f;
}

// ---------------------------------------------------------------------------
extern "C" void kernel_launch(void* const* d_in, const int* in_sizes, int n_in,
                              void* d_out, int out_size)
{
    const float* query = (const float*)d_in[0];
    const float* key   = (const float*)d_in[1];
    const float* value = (const float*)d_in[2];
    // d_in[3] sin_pos_enc: unused — rel_shift term is constant over the
    // softmax axis in the reference and cancels exactly.
    const float* W     = (const float*)d_in[4];   // (3E, E)
    const float* bias  = (const float*)d_in[5];   // (3E,)
    const float* out_w = (const float*)d_in[6];
    const float* out_b = (const float*)d_in[7];
    // d_in[8] rel_proj_w: unused (cancels)
    const float* rel_u = (const float*)d_in[9];   // (H,D) == E contiguous floats
    // d_in[10] rel_v: unused (cancels)

    float* out  = (float*)d_out;                      // (L, N, E)
    float* attw = out + (size_t)Ld * NBd * Ed;        // (N, L, S)

    const int QK_SMEM = (64 * QK_SA + 64 * QK_SB) * 4;   // 67584 B
    const int PV_SMEM = (32 * PV_SA + 32 * PV_SB) * 4;   // 41984 B
    const int PJ_SMEM = (32 * PJ_SA + 32 * PJ_SB) * 4;   // 41984 B
    cudaFuncSetAttribute(qk5_kernel,   cudaFuncAttributeMaxDynamicSharedMemorySize, QK_SMEM);
    cudaFuncSetAttribute(pv5_kernel,   cudaFuncAttributeMaxDynamicSharedMemorySize, PV_SMEM);
    cudaFuncSetAttribute(proj5_kernel, cudaFuncAttributeMaxDynamicSharedMemorySize, PJ_SMEM);

    dim3 gp(Ed / 64, Md / 256);
    // q_eff = (q + rel_u) / sqrt(D)
    proj5_kernel<<<gp, 256, PJ_SMEM>>>(query, W,               bias,          rel_u,   0.125f, 0, nullptr);
    proj5_kernel<<<gp, 256, PJ_SMEM>>>(key,   W + Ed * Ed,     bias + Ed,     nullptr, 1.0f,   1, nullptr);
    proj5_kernel<<<gp, 256, PJ_SMEM>>>(value, W + 2 * Ed * Ed, bias + 2 * Ed, nullptr, 1.0f,   2, nullptr);

    qk5_kernel<<<dim3(Sd / 128, Ld / 128, BATCHd), 256, QK_SMEM>>>();
    softmax_kernel<<<dim3(Ld, NBd), 256>>>(attw);
    pv5_kernel<<<dim3(Ld / 256, BATCHd), 256, PV_SMEM>>>();

    proj5_kernel<<<gp, 256, PJ_SMEM>>>(nullptr, out_w, out_b, nullptr, 1.0f, 3, out);
}

// round 16
// speedup vs baseline: 1.8698x; 1.8653x over previous
#include <cuda_runtime.h>
#include <cuda_bf16.h>
#include <math.h>

#define Ld 2048
#define Sd 2048
#define NBd 4
#define Ed 512
#define Hd 8
#define Dd 64
#define Md (Ld * NBd)
#define BATCHd (NBd * Hd)

typedef unsigned u32;
typedef __nv_bfloat16 bf16;

// ---- device scratch (allocation-free) ------------------------------------
__device__ bf16 g_xqh[(size_t)Md * Ed], g_xql[(size_t)Md * Ed];
__device__ bf16 g_xkh[(size_t)Md * Ed], g_xkl[(size_t)Md * Ed];
__device__ bf16 g_xvh[(size_t)Md * Ed], g_xvl[(size_t)Md * Ed];
__device__ bf16 g_wh[(size_t)4 * Ed * Ed], g_wl[(size_t)4 * Ed * Ed]; // in_proj(3E,E) + out_w(E,E)
__device__ bf16 g_qh[(size_t)BATCHd * Ld * Dd], g_ql[(size_t)BATCHd * Ld * Dd];
__device__ bf16 g_kh[(size_t)BATCHd * Sd * Dd], g_kl[(size_t)BATCHd * Sd * Dd];
__device__ bf16 g_vh[(size_t)BATCHd * Sd * Dd], g_vl[(size_t)BATCHd * Sd * Dd];
__device__ float g_sc[(size_t)BATCHd * Ld * Sd];                      // fp32 scores
__device__ bf16 g_ph[(size_t)BATCHd * Ld * Sd], g_pl[(size_t)BATCHd * Ld * Sd];
__device__ bf16 g_aoh[(size_t)Md * Ed], g_aol[(size_t)Md * Ed];

// ---- helpers ---------------------------------------------------------------
__device__ __forceinline__ void bsp(float x, bf16& h, bf16& l) {
    h = __float2bfloat16_rn(x);
    l = __float2bfloat16_rn(x - __bfloat162float(h));
}
__device__ __forceinline__ u32 pack2(bf16 a, bf16 b) {
    __nv_bfloat162 t = __halves2bfloat162(a, b);
    return *(u32*)&t;
}
__device__ __forceinline__ u32 s2u(const void* p) { return (u32)__cvta_generic_to_shared(p); }

__device__ __forceinline__ void ldm4(u32* r, u32 a) {
    asm volatile("ldmatrix.sync.aligned.m8n8.x4.shared.b16 {%0,%1,%2,%3},[%4];"
        : "=r"(r[0]), "=r"(r[1]), "=r"(r[2]), "=r"(r[3]) : "r"(a));
}
__device__ __forceinline__ void ldm4t(u32* r, u32 a) {
    asm volatile("ldmatrix.sync.aligned.m8n8.x4.trans.shared.b16 {%0,%1,%2,%3},[%4];"
        : "=r"(r[0]), "=r"(r[1]), "=r"(r[2]), "=r"(r[3]) : "r"(a));
}
__device__ __forceinline__ void mma16816(float* d, const u32* a, const u32* b) {
    asm volatile("mma.sync.aligned.m16n8k16.row.col.f32.bf16.bf16.f32 "
        "{%0,%1,%2,%3},{%4,%5,%6,%7},{%8,%9},{%0,%1,%2,%3};"
        : "+f"(d[0]), "+f"(d[1]), "+f"(d[2]), "+f"(d[3])
        : "r"(a[0]), "r"(a[1]), "r"(a[2]), "r"(a[3]), "r"(b[0]), "r"(b[1]));
}

// ---- fp32 -> bf16 hi/lo conversion ----------------------------------------
// dst: 0=query 1=key 2=value 3=in_proj_weight(off 0) 4=out_w(off 3*E*E)
__global__ void cvt_kernel(const float* __restrict__ src, int dst, int n4)
{
    int i = blockIdx.x * 256 + threadIdx.x;
    if (i >= n4) return;
    bf16 *hi, *lo;
    if (dst == 0) { hi = g_xqh; lo = g_xql; }
    else if (dst == 1) { hi = g_xkh; lo = g_xkl; }
    else if (dst == 2) { hi = g_xvh; lo = g_xvl; }
    else if (dst == 3) { hi = g_wh; lo = g_wl; }
    else { hi = g_wh + (size_t)3 * Ed * Ed; lo = g_wl + (size_t)3 * Ed * Ed; }
    float4 v = ((const float4*)src)[i];
    bf16 h0, l0, h1, l1, h2, l2, h3, l3;
    bsp(v.x, h0, l0); bsp(v.y, h1, l1); bsp(v.z, h2, l2); bsp(v.w, h3, l3);
    ((u32*)hi)[2 * i]     = pack2(h0, h1);
    ((u32*)hi)[2 * i + 1] = pack2(h2, h3);
    ((u32*)lo)[2 * i]     = pack2(l0, l1);
    ((u32*)lo)[2 * i + 1] = pack2(l2, l3);
}

// ===========================================================================
// proj: Y = X @ W^T (+bias +rel)*scale.  Tile 128m x 128e, 8 warps (64x32 each),
// k-tile 64, K=512. 3-product bf16 split MMA. mode 0/1/2 scatter hi/lo to
// q/k/v [b][l|s][d]; mode 3 -> fp32 out.
// ===========================================================================
__global__ void __launch_bounds__(256, 2) projT_kernel(
    int mode, const float* __restrict__ bias, const float* __restrict__ rel,
    float scale, float* __restrict__ outp)
{
    extern __shared__ bf16 sm[];
    bf16* XH = sm;            // [128][72]
    bf16* XL = sm + 9216;
    bf16* WH = sm + 18432;
    bf16* WL = sm + 27648;

    const bf16 *Xh, *Xl;
    if (mode == 0)      { Xh = g_xqh; Xl = g_xql; }
    else if (mode == 1) { Xh = g_xkh; Xl = g_xkl; }
    else if (mode == 2) { Xh = g_xvh; Xl = g_xvl; }
    else                { Xh = g_aoh; Xl = g_aol; }
    const bf16* Wh = g_wh + (size_t)mode * Ed * Ed;   // mode==3 -> out_w slot
    const bf16* Wl = g_wl + (size_t)mode * Ed * Ed;

    int tid = threadIdx.x, lane = tid & 31, warp = tid >> 5;
    int e0 = blockIdx.x * 128, m0 = blockIdx.y * 128;
    int wm = warp >> 2, we = warp & 3;
    int mb = wm * 64, eb = we * 32;

    u32 XHu = s2u(XH), XLu = s2u(XL), WHu = s2u(WH), WLu = s2u(WL);
    u32 aoffs = 2 * (((mb + (lane & 15)) * 72) + ((lane >> 4) * 8));
    u32 boffs = 2 * (((eb + (lane & 7) + ((lane >> 4) << 3)) * 72) + (((lane >> 3) & 1) << 3));

    float acc[16][4];
    #pragma unroll
    for (int i = 0; i < 16; i++) acc[i][0] = acc[i][1] = acc[i][2] = acc[i][3] = 0.f;

    for (int kt = 0; kt < Ed; kt += 64) {
        __syncthreads();
        #pragma unroll
        for (int u = 0; u < 4; u++) {
            int idx = tid + u * 256;
            int r = idx >> 3, c = (idx & 7) * 8;
            *(uint4*)(XH + r * 72 + c) = *(const uint4*)(Xh + (size_t)(m0 + r) * Ed + kt + c);
            *(uint4*)(XL + r * 72 + c) = *(const uint4*)(Xl + (size_t)(m0 + r) * Ed + kt + c);
            *(uint4*)(WH + r * 72 + c) = *(const uint4*)(Wh + (size_t)(e0 + r) * Ed + kt + c);
            *(uint4*)(WL + r * 72 + c) = *(const uint4*)(Wl + (size_t)(e0 + r) * Ed + kt + c);
        }
        __syncthreads();

        #pragma unroll
        for (int ks = 0; ks < 64; ks += 16) {
            u32 bh[2][4], bl[2][4];
            ldm4(bh[0], WHu + boffs + 2 * ks);
            ldm4(bh[1], WHu + boffs + 2 * (16 * 72 + ks));
            ldm4(bl[0], WLu + boffs + 2 * ks);
            ldm4(bl[1], WLu + boffs + 2 * (16 * 72 + ks));
            #pragma unroll
            for (int mi = 0; mi < 4; mi++) {
                u32 ah[4], al[4];
                ldm4(ah, XHu + aoffs + 2 * (mi * 16 * 72 + ks));
                ldm4(al, XLu + aoffs + 2 * (mi * 16 * 72 + ks));
                #pragma unroll
                for (int ni = 0; ni < 4; ni++) {
                    u32 bH[2] = { bh[ni >> 1][(ni & 1) * 2], bh[ni >> 1][(ni & 1) * 2 + 1] };
                    u32 bL[2] = { bl[ni >> 1][(ni & 1) * 2], bl[ni >> 1][(ni & 1) * 2 + 1] };
                    float* d = acc[mi * 4 + ni];
                    mma16816(d, ah, bH);
                    mma16816(d, ah, bL);
                    mma16816(d, al, bH);
                }
            }
        }
    }

    bf16* dh = (mode == 0) ? g_qh : (mode == 1) ? g_kh : g_vh;
    bf16* dl = (mode == 0) ? g_ql : (mode == 1) ? g_kl : g_vl;
    #pragma unroll
    for (int mi = 0; mi < 4; mi++) {
        #pragma unroll
        for (int ni = 0; ni < 4; ni++) {
            int r = m0 + mb + mi * 16 + (lane >> 2);
            int c = e0 + eb + ni * 8 + (lane & 3) * 2;
            float b0v = bias[c], b1v = bias[c + 1];
            float r0v = rel ? rel[c] : 0.f, r1v = rel ? rel[c + 1] : 0.f;
            const float* d = acc[mi * 4 + ni];
            float y00 = (d[0] + b0v + r0v) * scale;
            float y01 = (d[1] + b1v + r1v) * scale;
            float y10 = (d[2] + b0v + r0v) * scale;
            float y11 = (d[3] + b1v + r1v) * scale;
            if (mode == 3) {
                *(float2*)(outp + (size_t)r * Ed + c)       = make_float2(y00, y01);
                *(float2*)(outp + (size_t)(r + 8) * Ed + c) = make_float2(y10, y11);
            } else {
                int hh = c >> 6, dd = c & 63;
                {
                    int l = r >> 2, n = r & 3;
                    size_t idx = ((size_t)(n * Hd + hh) * Ld + l) * Dd + dd;
                    bf16 h0, l0_, h1, l1_;
                    bsp(y00, h0, l0_); bsp(y01, h1, l1_);
                    *(u32*)(dh + idx) = pack2(h0, h1);
                    *(u32*)(dl + idx) = pack2(l0_, l1_);
                }
                {
                    int r2 = r + 8;
                    int l = r2 >> 2, n = r2 & 3;
                    size_t idx = ((size_t)(n * Hd + hh) * Ld + l) * Dd + dd;
                    bf16 h0, l0_, h1, l1_;
                    bsp(y10, h0, l0_); bsp(y11, h1, l1_);
                    *(u32*)(dh + idx) = pack2(h0, h1);
                    *(u32*)(dl + idx) = pack2(l0_, l1_);
                }
            }
        }
    }
}

// ===========================================================================
// qk: scores[b][l][s] = q . k  (fp32 out). Tile 128l x 128s, D=64 resident.
// ===========================================================================
__global__ void __launch_bounds__(256, 2) qkT_kernel()
{
    extern __shared__ bf16 sm[];
    bf16* QH = sm;            // [128][72]
    bf16* QL = sm + 9216;
    bf16* KH = sm + 18432;
    bf16* KL = sm + 27648;

    int tid = threadIdx.x, lane = tid & 31, warp = tid >> 5;
    int s0 = blockIdx.x * 128, l0 = blockIdx.y * 128, b = blockIdx.z;
    int wm = warp >> 2, we = warp & 3;
    int mb = wm * 64, nb = we * 32;
    const bf16* Qh = g_qh + (size_t)b * Ld * Dd;
    const bf16* Ql = g_ql + (size_t)b * Ld * Dd;
    const bf16* Kh = g_kh + (size_t)b * Sd * Dd;
    const bf16* Kl = g_kl + (size_t)b * Sd * Dd;

    #pragma unroll
    for (int u = 0; u < 4; u++) {
        int idx = tid + u * 256;
        int r = idx >> 3, c = (idx & 7) * 8;
        *(uint4*)(QH + r * 72 + c) = *(const uint4*)(Qh + (size_t)(l0 + r) * Dd + c);
        *(uint4*)(QL + r * 72 + c) = *(const uint4*)(Ql + (size_t)(l0 + r) * Dd + c);
        *(uint4*)(KH + r * 72 + c) = *(const uint4*)(Kh + (size_t)(s0 + r) * Dd + c);
        *(uint4*)(KL + r * 72 + c) = *(const uint4*)(Kl + (size_t)(s0 + r) * Dd + c);
    }
    __syncthreads();

    u32 QHu = s2u(QH), QLu = s2u(QL), KHu = s2u(KH), KLu = s2u(KL);
    u32 aoffs = 2 * (((mb + (lane & 15)) * 72) + ((lane >> 4) * 8));
    u32 boffs = 2 * (((nb + (lane & 7) + ((lane >> 4) << 3)) * 72) + (((lane >> 3) & 1) << 3));

    float acc[16][4];
    #pragma unroll
    for (int i = 0; i < 16; i++) acc[i][0] = acc[i][1] = acc[i][2] = acc[i][3] = 0.f;

    #pragma unroll
    for (int ks = 0; ks < 64; ks += 16) {
        u32 bh[2][4], bl[2][4];
        ldm4(bh[0], KHu + boffs + 2 * ks);
        ldm4(bh[1], KHu + boffs + 2 * (16 * 72 + ks));
        ldm4(bl[0], KLu + boffs + 2 * ks);
        ldm4(bl[1], KLu + boffs + 2 * (16 * 72 + ks));
        #pragma unroll
        for (int mi = 0; mi < 4; mi++) {
            u32 ah[4], al[4];
            ldm4(ah, QHu + aoffs + 2 * (mi * 16 * 72 + ks));
            ldm4(al, QLu + aoffs + 2 * (mi * 16 * 72 + ks));
            #pragma unroll
            for (int ni = 0; ni < 4; ni++) {
                u32 bH[2] = { bh[ni >> 1][(ni & 1) * 2], bh[ni >> 1][(ni & 1) * 2 + 1] };
                u32 bL[2] = { bl[ni >> 1][(ni & 1) * 2], bl[ni >> 1][(ni & 1) * 2 + 1] };
                float* d = acc[mi * 4 + ni];
                mma16816(d, ah, bH);
                mma16816(d, ah, bL);
                mma16816(d, al, bH);
            }
        }
    }

    float* out = g_sc + (size_t)b * Ld * Sd;
    #pragma unroll
    for (int mi = 0; mi < 4; mi++) {
        #pragma unroll
        for (int ni = 0; ni < 4; ni++) {
            int r = l0 + mb + mi * 16 + (lane >> 2);
            int c = s0 + nb + ni * 8 + (lane & 3) * 2;
            const float* d = acc[mi * 4 + ni];
            *(float2*)(out + (size_t)r * Sd + c)       = make_float2(d[0], d[1]);
            *(float2*)(out + (size_t)(r + 8) * Sd + c) = make_float2(d[2], d[3]);
        }
    }
}

// ===========================================================================
// pv: out[b][l][d] = sum_s P V -> aoh/aol bf16 [m=(l,n)][e]. Tile 128l x 64d,
// k-tile 64. V consumed via ldmatrix.trans from natural [s][d].
// ===========================================================================
__global__ void __launch_bounds__(256, 2) pvT_kernel()
{
    extern __shared__ bf16 sm[];
    bf16* PH = sm;            // [128][72]
    bf16* PL = sm + 9216;
    bf16* VH = sm + 18432;    // [64][72]
    bf16* VL = sm + 23040;

    int tid = threadIdx.x, lane = tid & 31, warp = tid >> 5;
    int l0 = blockIdx.x * 128, b = blockIdx.y;
    int n = b >> 3, h = b & 7;
    int wm = warp >> 1, wd = warp & 1;
    int mb = wm * 32, db = wd * 32;
    const bf16* Ph = g_ph + (size_t)b * Ld * Sd;
    const bf16* Pl = g_pl + (size_t)b * Ld * Sd;
    const bf16* Vh = g_vh + (size_t)b * Sd * Dd;
    const bf16* Vl = g_vl + (size_t)b * Sd * Dd;

    u32 PHu = s2u(PH), PLu = s2u(PL), VHu = s2u(VH), VLu = s2u(VL);
    u32 aoffs = 2 * (((mb + (lane & 15)) * 72) + ((lane >> 4) * 8));
    u32 boffs = 2 * (((lane & 15) * 72) + db + ((lane >> 4) * 8));

    float acc[8][4];
    #pragma unroll
    for (int i = 0; i < 8; i++) acc[i][0] = acc[i][1] = acc[i][2] = acc[i][3] = 0.f;

    for (int st = 0; st < Sd; st += 64) {
        __syncthreads();
        #pragma unroll
        for (int u = 0; u < 4; u++) {
            int idx = tid + u * 256;
            int r = idx >> 3, c = (idx & 7) * 8;
            *(uint4*)(PH + r * 72 + c) = *(const uint4*)(Ph + (size_t)(l0 + r) * Sd + st + c);
            *(uint4*)(PL + r * 72 + c) = *(const uint4*)(Pl + (size_t)(l0 + r) * Sd + st + c);
        }
        #pragma unroll
        for (int u = 0; u < 2; u++) {
            int idx = tid + u * 256;
            int r = idx >> 3, c = (idx & 7) * 8;
            *(uint4*)(VH + r * 72 + c) = *(const uint4*)(Vh + (size_t)(st + r) * Dd + c);
            *(uint4*)(VL + r * 72 + c) = *(const uint4*)(Vl + (size_t)(st + r) * Dd + c);
        }
        __syncthreads();

        #pragma unroll
        for (int ks = 0; ks < 64; ks += 16) {
            u32 bh[2][4], bl[2][4];
            ldm4t(bh[0], VHu + boffs + 2 * (ks * 72));
            ldm4t(bh[1], VHu + boffs + 2 * (ks * 72 + 16));
            ldm4t(bl[0], VLu + boffs + 2 * (ks * 72));
            ldm4t(bl[1], VLu + boffs + 2 * (ks * 72 + 16));
            #pragma unroll
            for (int mi = 0; mi < 2; mi++) {
                u32 ah[4], al[4];
                ldm4(ah, PHu + aoffs + 2 * (mi * 16 * 72 + ks));
                ldm4(al, PLu + aoffs + 2 * (mi * 16 * 72 + ks));
                #pragma unroll
                for (int ni = 0; ni < 4; ni++) {
                    u32 bH[2] = { bh[ni >> 1][(ni & 1) * 2], bh[ni >> 1][(ni & 1) * 2 + 1] };
                    u32 bL[2] = { bl[ni >> 1][(ni & 1) * 2], bl[ni >> 1][(ni & 1) * 2 + 1] };
                    float* d = acc[mi * 4 + ni];
                    mma16816(d, ah, bH);
                    mma16816(d, ah, bL);
                    mma16816(d, al, bH);
                }
            }
        }
    }

    #pragma unroll
    for (int mi = 0; mi < 2; mi++) {
        #pragma unroll
        for (int ni = 0; ni < 4; ni++) {
            int r = l0 + mb + mi * 16 + (lane >> 2);
            int dd = db + ni * 8 + (lane & 3) * 2;
            const float* d = acc[mi * 4 + ni];
            size_t idx0 = ((size_t)r * NBd + n) * Ed + h * Dd + dd;
            size_t idx1 = ((size_t)(r + 8) * NBd + n) * Ed + h * Dd + dd;
            bf16 h0, l0_, h1, l1_;
            bsp(d[0], h0, l0_); bsp(d[1], h1, l1_);
            *(u32*)(g_aoh + idx0) = pack2(h0, h1);
            *(u32*)(g_aol + idx0) = pack2(l0_, l1_);
            bsp(d[2], h0, l0_); bsp(d[3], h1, l1_);
            *(u32*)(g_aoh + idx1) = pack2(h0, h1);
            *(u32*)(g_aol + idx1) = pack2(l0_, l1_);
        }
    }
}

// ===========================================================================
// Softmax over s (per l,n,h): reads fp32 scores, writes bf16 hi/lo probs +
// head-mean fp32 to att_weights.
// ===========================================================================
__global__ void __launch_bounds__(256) softmax_kernel(float* __restrict__ attw)
{
    int l = blockIdx.x, n = blockIdx.y;
    int tid = threadIdx.x;
    __shared__ float red[8];
    float mean[8] = {0, 0, 0, 0, 0, 0, 0, 0};

    for (int h = 0; h < Hd; h++) {
        size_t roff = ((size_t)(n * Hd + h) * Ld + l) * Sd;
        const float* row = g_sc + roff;
        bf16* ph = g_ph + roff;
        bf16* pl = g_pl + roff;
        float x[8];
        float mx = -1e30f;
        #pragma unroll
        for (int i = 0; i < 8; i++) {
            x[i] = row[tid + (i << 8)];
            mx = fmaxf(mx, x[i]);
        }
        #pragma unroll
        for (int o = 16; o; o >>= 1) mx = fmaxf(mx, __shfl_xor_sync(0xffffffffu, mx, o));
        if ((tid & 31) == 0) red[tid >> 5] = mx;
        __syncthreads();
        if (tid < 32) {
            float w = (tid < 8) ? red[tid] : -1e30f;
            #pragma unroll
            for (int o = 4; o; o >>= 1) w = fmaxf(w, __shfl_xor_sync(0xffffffffu, w, o));
            if (tid == 0) red[0] = w;
        }
        __syncthreads();
        mx = red[0];
        __syncthreads();

        float sum = 0.f;
        #pragma unroll
        for (int i = 0; i < 8; i++) {
            x[i] = __expf(x[i] - mx);
            sum += x[i];
        }
        #pragma unroll
        for (int o = 16; o; o >>= 1) sum += __shfl_xor_sync(0xffffffffu, sum, o);
        if ((tid & 31) == 0) red[tid >> 5] = sum;
        __syncthreads();
        if (tid < 32) {
            float w = (tid < 8) ? red[tid] : 0.f;
            #pragma unroll
            for (int o = 4; o; o >>= 1) w += __shfl_xor_sync(0xffffffffu, w, o);
            if (tid == 0) red[0] = w;
        }
        __syncthreads();
        float inv = 1.0f / red[0];
        __syncthreads();

        #pragma unroll
        for (int i = 0; i < 8; i++) {
            float p = x[i] * inv;
            mean[i] += p;
            bf16 hh, ll;
            bsp(p, hh, ll);
            ph[tid + (i << 8)] = hh;
            pl[tid + (i << 8)] = ll;
        }
    }

    float* aw = attw + ((size_t)n * Ld + l) * Sd;
    #pragma unroll
    for (int i = 0; i < 8; i++)
        aw[tid + (i << 8)] = mean[i] * 0.125f;
}

// ---------------------------------------------------------------------------
extern "C" void kernel_launch(void* const* d_in, const int* in_sizes, int n_in,
                              void* d_out, int out_size)
{
    const float* query = (const float*)d_in[0];
    const float* key   = (const float*)d_in[1];
    const float* value = (const float*)d_in[2];
    // d_in[3] sin_pos_enc: unused — rel_shift term is constant over the
    // softmax axis in the reference and cancels exactly.
    const float* W     = (const float*)d_in[4];   // (3E, E)
    const float* bias  = (const float*)d_in[5];   // (3E,)
    const float* out_w = (const float*)d_in[6];
    const float* out_b = (const float*)d_in[7];
    // d_in[8] rel_proj_w: unused (cancels)
    const float* rel_u = (const float*)d_in[9];   // (H,D) == E floats
    // d_in[10] rel_v: unused (cancels)

    float* out  = (float*)d_out;                  // (L, N, E)
    float* attw = out + (size_t)Ld * NBd * Ed;    // (N, L, S)

    const int GEMM_SMEM = 4 * 9216 * 2;           // 73728 B
    const int PV_SMEM   = (2 * 9216 + 2 * 4608) * 2;  // 55296 B
    cudaFuncSetAttribute(projT_kernel, cudaFuncAttributeMaxDynamicSharedMemorySize, GEMM_SMEM);
    cudaFuncSetAttribute(qkT_kernel,   cudaFuncAttributeMaxDynamicSharedMemorySize, GEMM_SMEM);
    cudaFuncSetAttribute(pvT_kernel,   cudaFuncAttributeMaxDynamicSharedMemorySize, PV_SMEM);

    // 1) fp32 -> bf16 hi/lo conversions
    cvt_kernel<<<(Md * Ed / 4 + 255) / 256, 256>>>(query, 0, Md * Ed / 4);
    cvt_kernel<<<(Md * Ed / 4 + 255) / 256, 256>>>(key,   1, Md * Ed / 4);
    cvt_kernel<<<(Md * Ed / 4 + 255) / 256, 256>>>(value, 2, Md * Ed / 4);
    cvt_kernel<<<(3 * Ed * Ed / 4 + 255) / 256, 256>>>(W,     3, 3 * Ed * Ed / 4);
    cvt_kernel<<<(Ed * Ed / 4 + 255) / 256, 256>>>(out_w, 4, Ed * Ed / 4);

    // 2) projections: q_eff = (q + rel_u)/8 folded into mode 0
    dim3 gp(Ed / 128, Md / 128);
    projT_kernel<<<gp, 256, GEMM_SMEM>>>(0, bias,          rel_u,   0.125f, nullptr);
    projT_kernel<<<gp, 256, GEMM_SMEM>>>(1, bias + Ed,     nullptr, 1.0f,   nullptr);
    projT_kernel<<<gp, 256, GEMM_SMEM>>>(2, bias + 2 * Ed, nullptr, 1.0f,   nullptr);

    // 3) attention
    qkT_kernel<<<dim3(Sd / 128, Ld / 128, BATCHd), 256, GEMM_SMEM>>>();
    softmax_kernel<<<dim3(Ld, NBd), 256>>>(attw);
    pvT_kernel<<<dim3(Ld / 128, BATCHd), 256, PV_SMEM>>>();

    // 4) output projection
    projT_kernel<<<gp, 256, GEMM_SMEM>>>(3, out_b, nullptr, 1.0f, out);
}